// round 9
// baseline (speedup 1.0000x reference)
#include <cuda_runtime.h>
#include <stdint.h>

#define GRID_W 512
#define CELLS  (GRID_W * GRID_W)   // 262144
#define NW     (CELLS / 32)        // 8192 words
#define MAXPTS 16384
#define MIN_P_CLUSTER 20

// -------- device scratch --------
__device__ unsigned int  g_occbits[NW];                  // cleaned by k_points_out
__device__ unsigned char g_core[CELLS];                  // idempotent across replays
__device__ int           g_parent[CELLS];                // re-seeded at claim time
__device__ int           g_raw[CELLS];                   // rewritten for occupied cells
__device__ int           g_count[CELLS];                 // cleaned by k_points_out
__device__ __align__(16) unsigned int g_mask[NW];        // idempotent across replays
__device__ int           g_rootlab[CELLS];               // idempotent across replays
__device__ int           g_list[MAXPTS];
__device__ int           g_ncells;                       // reset by k_points_out
__device__ int           g_ptcell[MAXPTS];

// -------- helpers --------
__device__ __forceinline__ int occbit(int x, int y) {
    if ((unsigned)x >= GRID_W || (unsigned)y >= GRID_W) return 0;
    int c = y * GRID_W + x;
    return (g_occbits[c >> 5] >> (c & 31)) & 1;
}

__device__ __forceinline__ bool is_core(int cx, int cy) {
    if (!occbit(cx, cy)) return false;
    int deg = 0;
#pragma unroll
    for (int dy = -1; dy <= 1; dy++)
#pragma unroll
        for (int dx = -1; dx <= 1; dx++)
            deg += occbit(cx + dx, cy + dy);
    return deg >= 5;
}

__device__ __forceinline__ int find_root_v(int v) {
    volatile int* p = (volatile int*)g_parent;
    int cur = v;
    int par = p[cur];
    while (par != cur) {
        int gp = p[par];
        if (gp != par) g_parent[cur] = gp;  // benign racy path-halving
        cur = par;
        par = p[cur];
    }
    return cur;
}

__device__ __forceinline__ void union_min_g(int a, int b) {
    int ra = a, rb = b;
    while (true) {
        ra = find_root_v(ra);
        rb = find_root_v(rb);
        if (ra == rb) return;
        int hi = max(ra, rb);
        int lo = min(ra, rb);
        int old = atomicCAS(&g_parent[hi], hi, lo);
        if (old == hi) return;
        ra = lo;
        rb = old;
    }
}

// -------- kernels --------

__global__ void k_scatter(const float* __restrict__ pts, int n) {
    int i = blockIdx.x * blockDim.x + threadIdx.x;
    if (i >= n) return;
    float x = pts[i * 5 + 1];
    float y = pts[i * 5 + 2];
    // match jnp: floor((p - (-51.2)) / 0.2) in fp32, IEEE div
    int cx = (int)floorf((x - (-51.2f)) / 0.2f);
    int cy = (int)floorf((y - (-51.2f)) / 0.2f);
    cx = min(max(cx, 0), GRID_W - 1);
    cy = min(max(cy, 0), GRID_W - 1);
    int cell = cy * GRID_W + cx;
    g_ptcell[i] = cell;
    unsigned bit = 1u << (cell & 31);
    unsigned old = atomicOr(&g_occbits[cell >> 5], bit);
    if (!(old & bit)) {
        g_parent[cell] = cell;
        int p = atomicAdd(&g_ncells, 1);
        g_list[p] = cell;
    }
}

// 4 threads per occupied cell; dir 0 persists the core flag.
__global__ void k_union() {
    int tid = blockIdx.x * blockDim.x + threadIdx.x;
    int idx = tid >> 2;
    int dir = tid & 3;
    if (idx >= g_ncells) return;
    int c = g_list[idx];
    int cx = c & (GRID_W - 1);
    int cy = c >> 9;
    bool cc = is_core(cx, cy);
    if (dir == 0) g_core[c] = cc ? 1 : 0;
    if (!cc) return;
    const int dxs[4] = { 1, -1, 0, 1 };
    const int dys[4] = { 0,  1, 1, 1 };
    int nx = cx + dxs[dir], ny = cy + dys[dir];
    if (!is_core(nx, ny)) return;
    union_min_g(c, ny * GRID_W + nx);
}

// fused flatten + raw (path-halving finds) + counts + root bitmask
__global__ void k_raw() {
    int idx = blockIdx.x * blockDim.x + threadIdx.x;
    if (idx >= g_ncells) return;
    int c = g_list[idx];
    int r;
    if (g_core[c]) {
        r = find_root_v(c);
    } else {
        int cx = c & (GRID_W - 1);
        int cy = c >> 9;
        r = 0x7fffffff;
#pragma unroll
        for (int dy = -1; dy <= 1; dy++) {
#pragma unroll
            for (int dx = -1; dx <= 1; dx++) {
                if (dx == 0 && dy == 0) continue;
                int nx = cx + dx, ny = cy + dy;
                if (!occbit(nx, ny)) continue;
                int nc = ny * GRID_W + nx;
                if (g_core[nc]) r = min(r, find_root_v(nc));
            }
        }
        if (r == 0x7fffffff) r = -1;
    }
    g_raw[c] = r;
    if (r >= 0) {
        if (atomicAdd(&g_count[r], 1) == 0)
            atomicOr(&g_mask[r >> 5], 1u << (r & 31));
    }
}

// single block, 256 threads: warp-shuffle prefix popcount over g_mask,
// per-root final labels, max kept label, output tail.
__global__ void k_scan(float* __restrict__ out, int n, int out_size) {
    const int NT = 256;
    const int WPT = NW / NT;  // 32 words per thread
    __shared__ int warpsum[8];
    __shared__ int warpmax[8];
    __shared__ int s_maxDense;
    int t = threadIdx.x;
    int lane = t & 31;
    int wid = t >> 5;

    // vectorized load: 8 x uint4 = 32 words
    unsigned w[WPT];
    const uint4* m4 = (const uint4*)g_mask;
#pragma unroll
    for (int j = 0; j < WPT / 4; j++) {
        uint4 v = m4[t * (WPT / 4) + j];
        w[j * 4 + 0] = v.x;
        w[j * 4 + 1] = v.y;
        w[j * 4 + 2] = v.z;
        w[j * 4 + 3] = v.w;
    }
    int s = 0;
#pragma unroll
    for (int j = 0; j < WPT; j++) s += __popc(w[j]);

    // warp-inclusive scan of per-thread sums
    int incl = s;
#pragma unroll
    for (int off = 1; off < 32; off <<= 1) {
        int v = __shfl_up_sync(0xffffffffu, incl, off);
        if (lane >= off) incl += v;
    }
    if (lane == 31) warpsum[wid] = incl;
    __syncthreads();
    if (wid == 0) {
        int v = (lane < 8) ? warpsum[lane] : 0;
#pragma unroll
        for (int off = 1; off < 8; off <<= 1) {
            int u = __shfl_up_sync(0xffffffffu, v, off);
            if (lane >= off) v += u;
        }
        if (lane < 8) warpsum[lane] = v;  // inclusive warp totals
    }
    __syncthreads();
    int rank = incl - s + (wid ? warpsum[wid - 1] : 0);  // exclusive prefix

    // walk set bits: write per-root labels, track max kept label
    int localMax = -1;
#pragma unroll
    for (int j = 0; j < WPT; j++) {
        unsigned bits = w[j];
        while (bits) {
            int b = __ffs(bits) - 1;
            bits &= bits - 1;
            int cell = (t * WPT + j) * 32 + b;
            bool keep = g_count[cell] >= MIN_P_CLUSTER;
            g_rootlab[cell] = keep ? rank : -1;
            if (keep) localMax = max(localMax, rank);
            rank++;
        }
    }
#pragma unroll
    for (int off = 16; off > 0; off >>= 1)
        localMax = max(localMax, __shfl_xor_sync(0xffffffffu, localMax, off));
    if (lane == 0) warpmax[wid] = localMax;
    __syncthreads();
    if (t == 0) {
        int m = -1;
#pragma unroll
        for (int j = 0; j < 8; j++) m = max(m, warpmax[j]);
        s_maxDense = m;
    }
    __syncthreads();
    for (int idx = n + t; idx < out_size; idx += NT)
        out[idx] = (idx == n) ? (float)(s_maxDense + 1) : 0.0f;
}

// per-point labels + cleanup for the next identical replay
__global__ void k_points_out(float* __restrict__ out, int n) {
    int i = blockIdx.x * blockDim.x + threadIdx.x;
    if (i >= n) return;
    int c = g_ptcell[i];
    int r = g_raw[c];
    out[i] = (r >= 0) ? (float)g_rootlab[r] : -1.0f;
    g_occbits[c >> 5] = 0u;      // all writers store 0 — race-benign
    if (r >= 0) g_count[r] = 0;  // every counted root has at least one point
    if (i == 0) g_ncells = 0;
}

// -------- launch --------
extern "C" void kernel_launch(void* const* d_in, const int* in_sizes, int n_in,
                              void* d_out, int out_size) {
    const float* pts = (const float*)d_in[0];
    int n = in_sizes[0] / 5;  // points are (N, 5)
    float* out = (float*)d_out;

    const int TB = 256;
    int ptBlocks = (n + TB - 1) / TB;
    int unionBlocks = (4 * n + TB - 1) / TB;

    k_scatter<<<ptBlocks, TB>>>(pts, n);
    k_union<<<unionBlocks, TB>>>();
    k_raw<<<ptBlocks, TB>>>();
    k_scan<<<1, TB>>>(out, n, out_size);
    k_points_out<<<ptBlocks, TB>>>(out, n);
}

// round 10
// speedup vs baseline: 1.1030x; 1.1030x over previous
#include <cuda_runtime.h>
#include <stdint.h>

#define GRID_W 512
#define CELLS  (GRID_W * GRID_W)   // 262144
#define NW     (CELLS / 32)        // 8192 words
#define MAXPTS 16384
#define MAXR   8192
#define MIN_P_CLUSTER 20

// -------- device scratch --------
__device__ unsigned int  g_occbits[NW];    // cleaned by k_points_out
__device__ unsigned char g_core[CELLS];    // idempotent across replays
__device__ int           g_parent[CELLS];  // re-seeded at claim time
__device__ int           g_raw[CELLS];     // rewritten for occupied cells
__device__ int           g_count[CELLS];   // cleaned by k_points_out
__device__ int           g_rootlab[CELLS]; // idempotent across replays
__device__ int           g_list[MAXPTS];
__device__ int           g_ncells;         // reset by k_points_out
__device__ int           g_ptcell[MAXPTS];
__device__ int           g_rootlist[MAXR]; // compact distinct roots
__device__ int           g_nroots;         // reset by k_points_out

// -------- helpers --------
__device__ __forceinline__ int occbit(int x, int y) {
    if ((unsigned)x >= GRID_W || (unsigned)y >= GRID_W) return 0;
    int c = y * GRID_W + x;
    return (g_occbits[c >> 5] >> (c & 31)) & 1;
}

__device__ __forceinline__ bool is_core(int cx, int cy) {
    if (!occbit(cx, cy)) return false;
    int deg = 0;
#pragma unroll
    for (int dy = -1; dy <= 1; dy++)
#pragma unroll
        for (int dx = -1; dx <= 1; dx++)
            deg += occbit(cx + dx, cy + dy);
    return deg >= 5;
}

__device__ __forceinline__ int find_root_v(int v) {
    volatile int* p = (volatile int*)g_parent;
    int cur = v;
    int par = p[cur];
    while (par != cur) {
        int gp = p[par];
        if (gp != par) g_parent[cur] = gp;  // benign racy path-halving
        cur = par;
        par = p[cur];
    }
    return cur;
}

__device__ __forceinline__ void union_min_g(int a, int b) {
    int ra = a, rb = b;
    while (true) {
        ra = find_root_v(ra);
        rb = find_root_v(rb);
        if (ra == rb) return;
        int hi = max(ra, rb);
        int lo = min(ra, rb);
        int old = atomicCAS(&g_parent[hi], hi, lo);
        if (old == hi) return;
        ra = lo;
        rb = old;
    }
}

// -------- kernels --------

__global__ void k_scatter(const float* __restrict__ pts, int n) {
    int i = blockIdx.x * blockDim.x + threadIdx.x;
    if (i >= n) return;
    float x = pts[i * 5 + 1];
    float y = pts[i * 5 + 2];
    // match jnp: floor((p - (-51.2)) / 0.2) in fp32, IEEE div
    int cx = (int)floorf((x - (-51.2f)) / 0.2f);
    int cy = (int)floorf((y - (-51.2f)) / 0.2f);
    cx = min(max(cx, 0), GRID_W - 1);
    cy = min(max(cy, 0), GRID_W - 1);
    int cell = cy * GRID_W + cx;
    g_ptcell[i] = cell;
    unsigned bit = 1u << (cell & 31);
    unsigned old = atomicOr(&g_occbits[cell >> 5], bit);
    if (!(old & bit)) {
        g_parent[cell] = cell;
        int p = atomicAdd(&g_ncells, 1);
        g_list[p] = cell;
    }
}

// 4 threads per occupied cell; dir 0 persists the core flag.
__global__ void k_union() {
    int tid = blockIdx.x * blockDim.x + threadIdx.x;
    int idx = tid >> 2;
    int dir = tid & 3;
    if (idx >= g_ncells) return;
    int c = g_list[idx];
    int cx = c & (GRID_W - 1);
    int cy = c >> 9;
    bool cc = is_core(cx, cy);
    if (dir == 0) g_core[c] = cc ? 1 : 0;
    if (!cc) return;
    const int dxs[4] = { 1, -1, 0, 1 };
    const int dys[4] = { 0,  1, 1, 1 };
    int nx = cx + dxs[dir], ny = cy + dys[dir];
    if (!is_core(nx, ny)) return;
    union_min_g(c, ny * GRID_W + nx);
}

// fused flatten + raw (path-halving finds) + counts + compact root list
__global__ void k_raw() {
    int idx = blockIdx.x * blockDim.x + threadIdx.x;
    if (idx >= g_ncells) return;
    int c = g_list[idx];
    int r;
    if (g_core[c]) {
        r = find_root_v(c);
    } else {
        int cx = c & (GRID_W - 1);
        int cy = c >> 9;
        r = 0x7fffffff;
#pragma unroll
        for (int dy = -1; dy <= 1; dy++) {
#pragma unroll
            for (int dx = -1; dx <= 1; dx++) {
                if (dx == 0 && dy == 0) continue;
                int nx = cx + dx, ny = cy + dy;
                if (!occbit(nx, ny)) continue;
                int nc = ny * GRID_W + nx;
                if (g_core[nc]) r = min(r, find_root_v(nc));
            }
        }
        if (r == 0x7fffffff) r = -1;
    }
    g_raw[c] = r;
    if (r >= 0) {
        if (atomicAdd(&g_count[r], 1) == 0) {
            int p = atomicAdd(&g_nroots, 1);
            g_rootlist[p] = r;   // each distinct root appended exactly once
        }
    }
}

// single block: rank R sparse roots by O(R^2) comparison (R ~ hundreds),
// write per-root final labels + maxDense + output tail.
__global__ void k_scan(float* __restrict__ out, int n, int out_size) {
    const int NT = 256;
    __shared__ int roots[MAXR];
    __shared__ int warpmax[8];
    __shared__ int s_maxDense;
    int t = threadIdx.x;
    int lane = t & 31;
    int wid = t >> 5;
    int R = g_nroots;

    for (int i = t; i < R; i += NT) roots[i] = g_rootlist[i];
    __syncthreads();

    int localMax = -1;
    for (int i = t; i < R; i += NT) {
        int r = roots[i];
        int rank = 0;
        for (int j = 0; j < R; j++) rank += (roots[j] < r) ? 1 : 0;
        bool keep = g_count[r] >= MIN_P_CLUSTER;
        g_rootlab[r] = keep ? rank : -1;
        if (keep) localMax = max(localMax, rank);
    }
#pragma unroll
    for (int off = 16; off > 0; off >>= 1)
        localMax = max(localMax, __shfl_xor_sync(0xffffffffu, localMax, off));
    if (lane == 0) warpmax[wid] = localMax;
    __syncthreads();
    if (t == 0) {
        int m = -1;
#pragma unroll
        for (int j = 0; j < 8; j++) m = max(m, warpmax[j]);
        s_maxDense = m;
    }
    __syncthreads();
    for (int idx = n + t; idx < out_size; idx += NT)
        out[idx] = (idx == n) ? (float)(s_maxDense + 1) : 0.0f;
}

// per-point labels + state cleanup for the next identical replay
__global__ void k_points_out(float* __restrict__ out, int n) {
    int i = blockIdx.x * blockDim.x + threadIdx.x;
    if (i >= n) return;
    int c = g_ptcell[i];
    int r = g_raw[c];
    out[i] = (r >= 0) ? (float)g_rootlab[r] : -1.0f;
    g_occbits[c >> 5] = 0u;      // all writers store 0 — race-benign
    if (r >= 0) g_count[r] = 0;  // every counted root has at least one point
    if (i == 0) { g_ncells = 0; g_nroots = 0; }
}

// -------- launch --------
extern "C" void kernel_launch(void* const* d_in, const int* in_sizes, int n_in,
                              void* d_out, int out_size) {
    const float* pts = (const float*)d_in[0];
    int n = in_sizes[0] / 5;  // points are (N, 5)
    float* out = (float*)d_out;

    const int TB = 256;
    int ptBlocks = (n + TB - 1) / TB;
    int unionBlocks = (4 * n + TB - 1) / TB;

    k_scatter<<<ptBlocks, TB>>>(pts, n);
    k_union<<<unionBlocks, TB>>>();
    k_raw<<<ptBlocks, TB>>>();
    k_scan<<<1, TB>>>(out, n, out_size);
    k_points_out<<<ptBlocks, TB>>>(out, n);
}

// round 11
// speedup vs baseline: 1.1879x; 1.0770x over previous
#include <cuda_runtime.h>
#include <stdint.h>

#define GRID_W 512
#define CELLS  (GRID_W * GRID_W)   // 262144
#define NW     (CELLS / 32)        // 8192 words
#define MAXPTS 16384
#define MAXR   8192
#define MIN_P_CLUSTER 20

// -------- device scratch --------
__device__ unsigned int  g_occbits[NW];    // cleaned by k_points_out
__device__ unsigned char g_core[CELLS];    // idempotent across replays
__device__ int           g_parent[CELLS];  // re-seeded at claim time
__device__ int           g_raw[CELLS];     // rewritten for occupied cells
__device__ int           g_count[CELLS];   // zeroed at claim time in k_scatter
__device__ int           g_list[MAXPTS];
__device__ int           g_ncells;         // reset by k_points_out
__device__ int           g_ptcell[MAXPTS];
__device__ int           g_rootlist[MAXR]; // compact distinct roots
__device__ int           g_nroots;         // reset by k_scatter (before k_raw fills)

// -------- helpers --------
__device__ __forceinline__ int occbit(int x, int y) {
    if ((unsigned)x >= GRID_W || (unsigned)y >= GRID_W) return 0;
    int c = y * GRID_W + x;
    return (g_occbits[c >> 5] >> (c & 31)) & 1;
}

__device__ __forceinline__ bool is_core(int cx, int cy) {
    if (!occbit(cx, cy)) return false;
    int deg = 0;
#pragma unroll
    for (int dy = -1; dy <= 1; dy++)
#pragma unroll
        for (int dx = -1; dx <= 1; dx++)
            deg += occbit(cx + dx, cy + dy);
    return deg >= 5;
}

__device__ __forceinline__ int find_root_v(int v) {
    volatile int* p = (volatile int*)g_parent;
    int cur = v;
    int par = p[cur];
    while (par != cur) {
        int gp = p[par];
        if (gp != par) g_parent[cur] = gp;  // benign racy path-halving
        cur = par;
        par = p[cur];
    }
    return cur;
}

__device__ __forceinline__ void union_min_g(int a, int b) {
    int ra = a, rb = b;
    while (true) {
        ra = find_root_v(ra);
        rb = find_root_v(rb);
        if (ra == rb) return;
        int hi = max(ra, rb);
        int lo = min(ra, rb);
        int old = atomicCAS(&g_parent[hi], hi, lo);
        if (old == hi) return;
        ra = lo;
        rb = old;
    }
}

// -------- kernels --------

__global__ void k_scatter(const float* __restrict__ pts, int n) {
    int i = blockIdx.x * blockDim.x + threadIdx.x;
    if (i == 0) g_nroots = 0;   // safe: consumed only by later kernels
    if (i >= n) return;
    float x = pts[i * 5 + 1];
    float y = pts[i * 5 + 2];
    // match jnp: floor((p - (-51.2)) / 0.2) in fp32, IEEE div
    int cx = (int)floorf((x - (-51.2f)) / 0.2f);
    int cy = (int)floorf((y - (-51.2f)) / 0.2f);
    cx = min(max(cx, 0), GRID_W - 1);
    cy = min(max(cy, 0), GRID_W - 1);
    int cell = cy * GRID_W + cx;
    g_ptcell[i] = cell;
    unsigned bit = 1u << (cell & 31);
    unsigned old = atomicOr(&g_occbits[cell >> 5], bit);
    if (!(old & bit)) {
        g_parent[cell] = cell;   // UF seed
        g_count[cell] = 0;       // count reset before k_raw increments
        int p = atomicAdd(&g_ncells, 1);
        g_list[p] = cell;
    }
}

// 4 threads per occupied cell; dir 0 persists the core flag.
__global__ void k_union() {
    int tid = blockIdx.x * blockDim.x + threadIdx.x;
    int idx = tid >> 2;
    int dir = tid & 3;
    if (idx >= g_ncells) return;
    int c = g_list[idx];
    int cx = c & (GRID_W - 1);
    int cy = c >> 9;
    bool cc = is_core(cx, cy);
    if (dir == 0) g_core[c] = cc ? 1 : 0;
    if (!cc) return;
    const int dxs[4] = { 1, -1, 0, 1 };
    const int dys[4] = { 0,  1, 1, 1 };
    int nx = cx + dxs[dir], ny = cy + dys[dir];
    if (!is_core(nx, ny)) return;
    union_min_g(c, ny * GRID_W + nx);
}

// fused flatten + raw (path-halving finds) + counts + compact root list
__global__ void k_raw() {
    int idx = blockIdx.x * blockDim.x + threadIdx.x;
    if (idx >= g_ncells) return;
    int c = g_list[idx];
    int r;
    if (g_core[c]) {
        r = find_root_v(c);
    } else {
        int cx = c & (GRID_W - 1);
        int cy = c >> 9;
        r = 0x7fffffff;
#pragma unroll
        for (int dy = -1; dy <= 1; dy++) {
#pragma unroll
            for (int dx = -1; dx <= 1; dx++) {
                if (dx == 0 && dy == 0) continue;
                int nx = cx + dx, ny = cy + dy;
                if (!occbit(nx, ny)) continue;
                int nc = ny * GRID_W + nx;
                if (g_core[nc]) r = min(r, find_root_v(nc));
            }
        }
        if (r == 0x7fffffff) r = -1;
    }
    g_raw[c] = r;
    if (r >= 0) {
        if (atomicAdd(&g_count[r], 1) == 0) {
            int p = atomicAdd(&g_nroots, 1);
            g_rootlist[p] = r;   // each distinct root appended exactly once
        }
    }
}

// per-point labels with inline rank (label = #roots < r, monotone in r),
// block 0 also computes maxDense + output tail; cleanup for next replay.
__global__ void k_points_out(float* __restrict__ out, int n, int out_size) {
    const int NT = 256;
    __shared__ int roots[MAXR];
    __shared__ int warpred[8];
    __shared__ int s_maxroot;
    __shared__ int s_total;
    int t = threadIdx.x;
    int lane = t & 31;
    int wid = t >> 5;
    int R = g_nroots;

    for (int k = t; k < R; k += NT) roots[k] = g_rootlist[k];
    __syncthreads();

    int i = blockIdx.x * NT + t;
    if (i < n) {
        int c = g_ptcell[i];
        int r = g_raw[c];
        int lab = -1;
        if (r >= 0 && g_count[r] >= MIN_P_CLUSTER) {
            int rank = 0;
            for (int j = 0; j < R; j++) rank += (roots[j] < r) ? 1 : 0;
            lab = rank;
        }
        out[i] = (float)lab;
        g_occbits[c >> 5] = 0u;  // all writers store 0 — race-benign
        if (i == 0) g_ncells = 0;
    }

    if (blockIdx.x == 0) {
        // max kept root by value
        int localMax = -1;
        for (int k = t; k < R; k += NT) {
            int r = roots[k];
            if (g_count[r] >= MIN_P_CLUSTER) localMax = max(localMax, r);
        }
#pragma unroll
        for (int off = 16; off > 0; off >>= 1)
            localMax = max(localMax, __shfl_xor_sync(0xffffffffu, localMax, off));
        if (lane == 0) warpred[wid] = localMax;
        __syncthreads();
        if (t == 0) {
            int m = -1;
#pragma unroll
            for (int j = 0; j < 8; j++) m = max(m, warpred[j]);
            s_maxroot = m;
        }
        __syncthreads();
        int maxroot = s_maxroot;
        // rank of max kept root = #roots < maxroot (parallel partial counts)
        int part = 0;
        if (maxroot >= 0)
            for (int k = t; k < R; k += NT) part += (roots[k] < maxroot) ? 1 : 0;
#pragma unroll
        for (int off = 16; off > 0; off >>= 1)
            part += __shfl_xor_sync(0xffffffffu, part, off);
        if (lane == 0) warpred[wid] = part;
        __syncthreads();
        if (t == 0) {
            int tot = 0;
#pragma unroll
            for (int j = 0; j < 8; j++) tot += warpred[j];
            s_total = (maxroot >= 0) ? (tot + 1) : 0;  // max_num_inst
        }
        __syncthreads();
        for (int idx = n + t; idx < out_size; idx += NT)
            out[idx] = (idx == n) ? (float)s_total : 0.0f;
    }
}

// -------- launch --------
extern "C" void kernel_launch(void* const* d_in, const int* in_sizes, int n_in,
                              void* d_out, int out_size) {
    const float* pts = (const float*)d_in[0];
    int n = in_sizes[0] / 5;  // points are (N, 5)
    float* out = (float*)d_out;

    const int TB = 256;
    int ptBlocks = (n + TB - 1) / TB;
    int unionBlocks = (4 * n + TB - 1) / TB;

    k_scatter<<<ptBlocks, TB>>>(pts, n);
    k_union<<<unionBlocks, TB>>>();
    k_raw<<<ptBlocks, TB>>>();
    k_points_out<<<ptBlocks, TB>>>(out, n, out_size);
}